// round 7
// baseline (speedup 1.0000x reference)
#include <cuda_runtime.h>
#include <cuda_fp16.h>
#include <cstddef>

#define NN 50000
#define NE 800000
#define DIN 128
#define DHID 128
#define DOUT 64
#define NB   ((NN + 1023) / 1024)   // 49 scan blocks

// ---------------- scratch (__device__ globals; no allocation) ----------------
__device__ __half g_xw1[(size_t)NN * DHID];   // fp16 x@W1 (RAW)
__device__ float  g_agg1[(size_t)NN * DHID];
__device__ __half g_xw2[(size_t)NN * DOUT];   // fp16 (relu(agg1)@W2)*dis
__device__ float  g_dis[NN];
__device__ int    g_cnt[NN];    // zero-init; restored to 0 by k_scanF
__device__ int    g_cur[NN];
__device__ int    g_off[NN + 1];
__device__ int    g_esrc[NE];
__device__ int    g_bsum[NB];
__device__ int    g_flag[NB];   // zero-init; restored to 0 by k_fill

// ---------------- CSR build ----------------
// histogram: 4 edges per thread via int4
__global__ void k_hist(const int* __restrict__ dst, int e4, int e) {
    int i = blockIdx.x * blockDim.x + threadIdx.x;
    if (i < e4) {
        int4 d = *(const int4*)(dst + i * 4);
        atomicAdd(&g_cnt[d.x], 1);
        atomicAdd(&g_cnt[d.y], 1);
        atomicAdd(&g_cnt[d.z], 1);
        atomicAdd(&g_cnt[d.w], 1);
    }
    int t = e4 * 4 + i;
    if (i < (e - e4 * 4)) atomicAdd(&g_cnt[dst[t]], 1);
}

// fused single-pass scan (decoupled lookback over <=49 blocks):
// g_off = exclusive prefix of g_cnt; g_cur = g_off; g_dis = rsqrt(cnt+1);
// g_cnt reset to 0; last block writes g_off[n].
__global__ void k_scanF(int n, int nb) {
    __shared__ int warpsum[32];
    __shared__ int s_pre;
    const int tid = threadIdx.x, lane = tid & 31, wid = tid >> 5;
    const int bid = blockIdx.x;
    int i = bid * 1024 + tid;
    int v = (i < n) ? g_cnt[i] : 0;
    int x = v;
#pragma unroll
    for (int o = 1; o < 32; o <<= 1) {
        int t = __shfl_up_sync(0xFFFFFFFFu, x, o);
        if (lane >= o) x += t;
    }
    if (lane == 31) warpsum[wid] = x;
    __syncthreads();
    if (wid == 0) {
        int w = warpsum[lane];
#pragma unroll
        for (int o = 1; o < 32; o <<= 1) {
            int t = __shfl_up_sync(0xFFFFFFFFu, w, o);
            if (lane >= o) w += t;
        }
        warpsum[lane] = w;
    }
    __syncthreads();
    int warpbase = (wid == 0) ? 0 : warpsum[wid - 1];
    int local = warpbase + x - v;               // block-local exclusive

    // publish block total, then look back over predecessors
    if (tid == 0) {
        g_bsum[bid] = warpsum[31];
        __threadfence();
        atomicExch(&g_flag[bid], 1);
    }
    if (wid == 0) {
        int p = 0;
        for (int idx = lane; idx < bid; idx += 32) {
            while (atomicAdd(&g_flag[idx], 0) == 0) {}
            p += atomicAdd(&g_bsum[idx], 0);
        }
#pragma unroll
        for (int o = 16; o > 0; o >>= 1)
            p += __shfl_down_sync(0xFFFFFFFFu, p, o);
        if (lane == 0) s_pre = p;
    }
    __syncthreads();
    int pre = s_pre;
    if (i < n) {
        int o = local + pre;
        g_off[i] = o;
        g_cur[i] = o;
        g_dis[i] = rsqrtf((float)v + 1.0f);
        g_cnt[i] = 0;                            // restore for next replay
    }
    if (bid == nb - 1 && tid == 0) g_off[n] = pre + warpsum[31];
}

// fill: 4 edges per thread (4 independent atomic chains); resets scan flags
__global__ void k_fill(const int* __restrict__ src, const int* __restrict__ dst,
                       int e4, int e, int nb) {
    int i = blockIdx.x * blockDim.x + threadIdx.x;
    if (i < nb) g_flag[i] = 0;                   // restore for next replay
    if (i < e4) {
        int4 d = *(const int4*)(dst + i * 4);
        int4 s = *(const int4*)(src + i * 4);
        int p0 = atomicAdd(&g_cur[d.x], 1);
        int p1 = atomicAdd(&g_cur[d.y], 1);
        int p2 = atomicAdd(&g_cur[d.z], 1);
        int p3 = atomicAdd(&g_cur[d.w], 1);
        g_esrc[p0] = s.x;
        g_esrc[p1] = s.y;
        g_esrc[p2] = s.z;
        g_esrc[p3] = s.w;
    }
    int t = e4 * 4 + i;
    if (i < (e - e4 * 4)) {
        int p = atomicAdd(&g_cur[dst[t]], 1);
        g_esrc[p] = src[t];
    }
}

// ---------------- packed f32x2 FMA helpers ----------------
__device__ __forceinline__ void fma2(unsigned long long& d,
                                     unsigned long long a,
                                     unsigned long long b) {
    asm("fma.rn.f32x2 %0, %1, %2, %0;" : "+l"(d) : "l"(a), "l"(b));
}
__device__ __forceinline__ unsigned long long bcast2(float a) {
    unsigned long long r;
    asm("mov.b64 %0, {%1, %1};" : "=l"(r) : "r"(__float_as_uint(a)));
    return r;
}

// ---------------- SGEMM (FFMA2): XWS(half) = (op(A) @ W) [* dis[row]] --------
template <int BN, int TN, bool RELU_IN, bool SCALE_DIS>
__global__ void __launch_bounds__(256, 2)
gemm_xws(const float* __restrict__ A, const float* __restrict__ W,
         __half* __restrict__ XWS, int M, int K, int N)
{
    constexpr int BM = 128, BK = 16, TM = 8;
    __shared__ float As[BK][BM];
    __shared__ float Bs[BK][BN];

    const int tid  = threadIdx.x;           // 256 threads
    const int row0 = blockIdx.x * BM;
    const int tx   = tid & 15;
    const int ty   = tid >> 4;

    unsigned long long acc2[TM][TN / 2];
#pragma unroll
    for (int i = 0; i < TM; i++)
#pragma unroll
        for (int j = 0; j < TN / 2; j++) acc2[i][j] = 0ULL;

    for (int k0 = 0; k0 < K; k0 += BK) {
#pragma unroll
        for (int l = 0; l < 2; l++) {
            int idx = tid + l * 256;
            int r   = idx >> 2;
            int c4  = (idx & 3) * 4;
            float4 av = make_float4(0.f, 0.f, 0.f, 0.f);
            int gr = row0 + r;
            if (gr < M) av = *(const float4*)(A + (size_t)gr * K + k0 + c4);
            if (RELU_IN) {
                av.x = fmaxf(av.x, 0.f); av.y = fmaxf(av.y, 0.f);
                av.z = fmaxf(av.z, 0.f); av.w = fmaxf(av.w, 0.f);
            }
            As[c4 + 0][r] = av.x;
            As[c4 + 1][r] = av.y;
            As[c4 + 2][r] = av.z;
            As[c4 + 3][r] = av.w;
        }
#pragma unroll
        for (int l = 0; l < (BK * BN / 4) / 256; l++) {
            int idx = tid + l * 256;
            int r   = idx / (BN / 4);
            int c4  = (idx % (BN / 4)) * 4;
            *(float4*)&Bs[r][c4] = *(const float4*)(W + (size_t)(k0 + r) * N + c4);
        }
        __syncthreads();

#pragma unroll
        for (int k = 0; k < BK; k++) {
            float a[TM];
            unsigned long long bp[TN / 2];
#pragma unroll
            for (int i = 0; i < TM; i += 4)
                *(float4*)&a[i] = *(const float4*)&As[k][ty * TM + i];
#pragma unroll
            for (int j = 0; j < TN / 2; j++)
                bp[j] = *(const unsigned long long*)&Bs[k][tx * TN + 2 * j];
#pragma unroll
            for (int i = 0; i < TM; i++) {
                unsigned long long ap = bcast2(a[i]);
#pragma unroll
                for (int j = 0; j < TN / 2; j++)
                    fma2(acc2[i][j], ap, bp[j]);
            }
        }
        __syncthreads();
    }

#pragma unroll
    for (int i = 0; i < TM; i++) {
        int gr = row0 + ty * TM + i;
        if (gr >= M) continue;
        float d = SCALE_DIS ? g_dis[gr] : 1.0f;
        __half2 h[TN / 2];
#pragma unroll
        for (int j = 0; j < TN / 2; j++) {
            float2 p = *(float2*)&acc2[i][j];
            h[j] = SCALE_DIS ? __floats2half2_rn(p.x * d, p.y * d)
                             : __floats2half2_rn(p.x, p.y);
        }
        __half* dstp = XWS + (size_t)gr * N + tx * TN;
        if (TN == 8) *(uint4*)dstp = *(uint4*)h;
        else         *(uint2*)dstp = *(uint2*)h;
    }
}

// ---------------- CSR aggregation, D=128 (half xw): one warp per node -------
__global__ void agg128h(const __half* __restrict__ xw,
                        const float* __restrict__ bias,
                        float* __restrict__ out, int n)
{
    int w = (blockIdx.x * blockDim.x + threadIdx.x) >> 5;
    int lane = threadIdx.x & 31;
    if (w >= n) return;
    int beg = g_off[w], end = g_off[w + 1];
    float dd = g_dis[w];

    uint2 us = *(const uint2*)(xw + (size_t)w * 128 + lane * 4);
    float2 s0 = __half22float2(*(__half2*)&us.x);
    float2 s1 = __half22float2(*(__half2*)&us.y);
    float4 acc = make_float4(s0.x * dd, s0.y * dd, s1.x * dd, s1.y * dd);

    int j = beg;
    for (; j + 4 <= end; j += 4) {
        int e0 = g_esrc[j], e1 = g_esrc[j + 1], e2 = g_esrc[j + 2], e3 = g_esrc[j + 3];
        float n0 = g_dis[e0], n1 = g_dis[e1], n2 = g_dis[e2], n3 = g_dis[e3];
        uint2 u0 = *(const uint2*)(xw + (size_t)e0 * 128 + lane * 4);
        uint2 u1 = *(const uint2*)(xw + (size_t)e1 * 128 + lane * 4);
        uint2 u2 = *(const uint2*)(xw + (size_t)e2 * 128 + lane * 4);
        uint2 u3 = *(const uint2*)(xw + (size_t)e3 * 128 + lane * 4);
        float2 a0 = __half22float2(*(__half2*)&u0.x), b0 = __half22float2(*(__half2*)&u0.y);
        float2 a1 = __half22float2(*(__half2*)&u1.x), b1 = __half22float2(*(__half2*)&u1.y);
        float2 a2 = __half22float2(*(__half2*)&u2.x), b2 = __half22float2(*(__half2*)&u2.y);
        float2 a3 = __half22float2(*(__half2*)&u3.x), b3 = __half22float2(*(__half2*)&u3.y);
        acc.x += a0.x * n0 + a1.x * n1 + a2.x * n2 + a3.x * n3;
        acc.y += a0.y * n0 + a1.y * n1 + a2.y * n2 + a3.y * n3;
        acc.z += b0.x * n0 + b1.x * n1 + b2.x * n2 + b3.x * n3;
        acc.w += b0.y * n0 + b1.y * n1 + b2.y * n2 + b3.y * n3;
    }
    for (; j < end; j++) {
        int s = g_esrc[j];
        float ns = g_dis[s];
        uint2 u = *(const uint2*)(xw + (size_t)s * 128 + lane * 4);
        float2 a = __half22float2(*(__half2*)&u.x);
        float2 b = __half22float2(*(__half2*)&u.y);
        acc.x += a.x * ns; acc.y += a.y * ns; acc.z += b.x * ns; acc.w += b.y * ns;
    }
    float4 bv = *(const float4*)(bias + lane * 4);
    acc.x = acc.x * dd + bv.x;
    acc.y = acc.y * dd + bv.y;
    acc.z = acc.z * dd + bv.z;
    acc.w = acc.w * dd + bv.w;
    *(float4*)(out + (size_t)w * 128 + lane * 4) = acc;
}

// ---------------- CSR aggregation, D=64 (half xws pre-scaled) ---------------
__global__ void agg64h(const __half* __restrict__ xws,
                       const float* __restrict__ bias,
                       float* __restrict__ out, int n)
{
    int w = (blockIdx.x * blockDim.x + threadIdx.x) >> 5;
    int lane = threadIdx.x & 31;
    if (w >= n) return;
    int beg = g_off[w], end = g_off[w + 1];
    float dd = g_dis[w];

    float2 acc = __half22float2(*(const __half2*)(xws + (size_t)w * 64 + lane * 2));

    int j = beg;
    for (; j + 4 <= end; j += 4) {
        int e0 = g_esrc[j], e1 = g_esrc[j + 1], e2 = g_esrc[j + 2], e3 = g_esrc[j + 3];
        float2 v0 = __half22float2(*(const __half2*)(xws + (size_t)e0 * 64 + lane * 2));
        float2 v1 = __half22float2(*(const __half2*)(xws + (size_t)e1 * 64 + lane * 2));
        float2 v2 = __half22float2(*(const __half2*)(xws + (size_t)e2 * 64 + lane * 2));
        float2 v3 = __half22float2(*(const __half2*)(xws + (size_t)e3 * 64 + lane * 2));
        acc.x += v0.x + v1.x + v2.x + v3.x;
        acc.y += v0.y + v1.y + v2.y + v3.y;
    }
    for (; j < end; j++) {
        int s = g_esrc[j];
        float2 v = __half22float2(*(const __half2*)(xws + (size_t)s * 64 + lane * 2));
        acc.x += v.x; acc.y += v.y;
    }
    float2 b = *(const float2*)(bias + lane * 2);
    acc.x = acc.x * dd + b.x;
    acc.y = acc.y * dd + b.y;
    *(float2*)(out + (size_t)w * 64 + lane * 2) = acc;
}

extern "C" void kernel_launch(void* const* d_in, const int* in_sizes, int n_in,
                              void* d_out, int out_size)
{
    const float* x  = (const float*)d_in[0];
    const int*   ei = (const int*)  d_in[1];
    const float* W1 = (const float*)d_in[2];
    const float* b1 = (const float*)d_in[3];
    const float* W2 = (const float*)d_in[4];
    const float* b2 = (const float*)d_in[5];
    float* out = (float*)d_out;

    const int N = in_sizes[0] / DIN;   // 50000
    const int E = in_sizes[1] / 2;     // 800000
    const int* src = ei;
    const int* dst = ei + E;

    __half *xw1, *xw2;
    float  *agg1;
    cudaGetSymbolAddress((void**)&xw1,  g_xw1);
    cudaGetSymbolAddress((void**)&agg1, g_agg1);
    cudaGetSymbolAddress((void**)&xw2,  g_xw2);

    static cudaStream_t s_side = nullptr;
    static cudaEvent_t  s_fork = nullptr, s_join = nullptr;
    if (s_side == nullptr) {
        cudaStreamCreateWithFlags(&s_side, cudaStreamNonBlocking);
        cudaEventCreateWithFlags(&s_fork, cudaEventDisableTiming);
        cudaEventCreateWithFlags(&s_join, cudaEventDisableTiming);
    }

    const int nb = (N + 1023) / 1024;
    const int e4 = E / 4;
    const int gemm_grid = (N + 127) / 128;

    // ---- fork: CSR build chain on side stream, GEMM1 on main stream ----
    cudaEventRecord(s_fork, 0);
    cudaStreamWaitEvent(s_side, s_fork, 0);

    k_hist <<<(e4 + 255) / 256, 256, 0, s_side>>>(dst, e4, E);
    k_scanF<<<nb, 1024, 0, s_side>>>(N, nb);
    k_fill <<<(e4 + 255) / 256, 256, 0, s_side>>>(src, dst, e4, E, nb);
    cudaEventRecord(s_join, s_side);

    // main: layer-1 GEMM (independent of graph structure), fp16 output
    gemm_xws<128, 8, false, false><<<gemm_grid, 256>>>(x, W1, xw1, N, DIN, DHID);

    cudaStreamWaitEvent(0, s_join, 0);

    // layer 1 aggregation (fp16 gathers, fp32 accumulate/output)
    agg128h<<<(N * 32 + 255) / 256, 256>>>(xw1, b1, agg1, N);

    // layer 2: fp16 output scaled by dis
    gemm_xws<64, 4, true, true><<<gemm_grid, 256>>>(agg1, W2, xw2, N, DHID, DOUT);
    agg64h<<<(N * 32 + 255) / 256, 256>>>(xw2, b2, out, N);
}